// round 12
// baseline (speedup 1.0000x reference)
#include <cuda_runtime.h>
#include <cstdint>

typedef unsigned long long ull;

#define BB 4
#define CC 384
#define HH 56
#define WW 56
#define HW (HH*WW)   // 3136
#define KK 5
#define KK2 25
#define SS 7
#define SS2 49
#define D2 192
#define SPM 64       // padded M row: 4 segments x 16 slots (14 real + 2 pad)
#define SEG 14
#define CTXP 52      // padded ctx_p row (even -> 8B-aligned float2)
#define KFP 52       // padded kf row

__device__ __align__(16) float g_ctx_p[BB*CC*CTXP];
__device__ __align__(16) float g_kf[BB*D2*KFP + 8];
__device__ __align__(16) float g_M[BB*CC*SPM];
__device__ __align__(16) float g_dyn[BB*KK2*HW];

#define FMA2(acc, a, b) asm("fma.rn.f32x2 %0, %1, %2, %0;" : "+l"(acc) : "l"(a), "l"(b))

__device__ __forceinline__ ull packf2(float lo, float hi) {
    ull r;
    asm("mov.b64 %0, {%1, %2};" : "=l"(r) : "r"(__float_as_uint(lo)), "r"(__float_as_uint(hi)));
    return r;
}
__device__ __forceinline__ float2 unpackf2(ull v) {
    uint32_t l, h;
    asm("mov.b64 {%0, %1}, %2;" : "=r"(l), "=r"(h) : "l"(v));
    float2 r; r.x = __uint_as_float(l); r.y = __uint_as_float(h);
    return r;
}

// ---------------------------------------------------------------------------
// K1 v2: adaptive avg pool, atomic-free (shfl reduce). Padded-row output.
// ---------------------------------------------------------------------------
__global__ void __launch_bounds__(256) pool_kernel(const float* __restrict__ ctx) {
    __shared__ float part[HH][SS];
    int t = threadIdx.x;
    int w = t >> 5;
    int l = t & 31;
    int bc = blockIdx.x;
    const float* p = ctx + (size_t)bc * HW;

    #pragma unroll
    for (int it = 0; it < 7; it++) {
        int h = w + it*8;
        float v = 0.f;
        if (l < 28) {
            float2 d2 = *(const float2*)(p + h*WW + 2*l);
            v = d2.x + d2.y;
        }
        v += __shfl_xor_sync(0xFFFFFFFFu, v, 1);
        v += __shfl_xor_sync(0xFFFFFFFFu, v, 2);
        if (l < 28 && (l & 3) == 0)
            part[h][l >> 2] = v;
    }
    __syncthreads();
    if (t < SS2) {
        int s1 = t / SS, s2 = t - s1*SS;
        float s = 0.f;
        #pragma unroll
        for (int i = 0; i < 8; i++) s += part[s1*8 + i][s2];
        g_ctx_p[(size_t)bc * CTXP + t] = s * (1.f/64.f);
    }
}

// ---------------------------------------------------------------------------
// K2 v2: kf[b,d,s0..s0+1] per thread (float2 cp loads, wk broadcast).
// ---------------------------------------------------------------------------
__global__ void kf_kernel(const float* __restrict__ Wk) {
    int id = blockIdx.x * blockDim.x + threadIdx.x;
    if (id >= BB*D2*25) return;
    int g = id % 25;
    int d = (id / 25) % D2;
    int b = id / (25*D2);
    int s0 = 2*g;
    const float* wk = Wk + (size_t)d * CC;
    const float* cp = g_ctx_p + (size_t)b * CC * CTXP + s0;
    float a0 = 0.f, a1 = 0.f;
    #pragma unroll 8
    for (int c = 0; c < CC; c++) {
        float w = wk[c];
        float2 v = *(const float2*)(cp + (size_t)c * CTXP);
        a0 += w * v.x;
        a1 += w * v.y;
    }
    float* o = g_kf + ((size_t)b*D2 + d)*KFP + s0;
    o[0] = a0;
    if (s0 + 1 < SS2) o[1] = a1;
}

// ---------------------------------------------------------------------------
// K3 v2: M[b,c,4 slots] per thread. c fastest -> coalesced Wq; kf broadcast.
// slot group q: seg=q>>2, k0=(q&3)*4, s0=seg*14+k0 (even -> float2 loads).
// ---------------------------------------------------------------------------
__global__ void m_kernel(const float* __restrict__ Wq) {
    int id = blockIdx.x * blockDim.x + threadIdx.x;
    if (id >= BB*CC*16) return;
    int c = id % CC;
    int q = (id / CC) & 15;
    int b = id / (CC*16);
    int seg = q >> 2, k0 = (q & 3) * 4;
    int s0 = seg*SEG + k0;

    const float* kf = g_kf + (size_t)b * D2 * KFP + s0;
    const float* wq = Wq + c;
    float a0=0.f, a1=0.f, a2=0.f, a3=0.f;
    #pragma unroll 4
    for (int d = 0; d < D2; d++) {
        float w = wq[(size_t)d * CC];
        float2 v0 = *(const float2*)(kf + (size_t)d * KFP);
        float2 v1 = *(const float2*)(kf + (size_t)d * KFP + 2);
        a0 += w * v0.x;
        a1 += w * v0.y;
        a2 += w * v1.x;
        a3 += w * v1.y;
    }
    float4 o;
    o.x = (k0+0 < SEG && s0+0 < SS2) ? a0 : 0.f;
    o.y = (k0+1 < SEG && s0+1 < SS2) ? a1 : 0.f;
    o.z = (k0+2 < SEG && s0+2 < SS2) ? a2 : 0.f;
    o.w = (k0+3 < SEG && s0+3 < SS2) ? a3 : 0.f;
    *(float4*)(g_M + ((size_t)b*CC + c)*SPM + seg*16 + k0) = o;
}

// ---------------------------------------------------------------------------
// K4 v7: PX=32, 256 threads = (16 px-pairs) x (4 s-groups) x (4 c-quarters).
// Parallel softmax epilogue (8 threads/pixel, shfl). Grid 392.
// ---------------------------------------------------------------------------
#define PX 32
#define AT 256
#define KCH 16
#define NCH 6               // chunks of 16 c per quarter (96/16)
#define CQG 96              // channels per quarter
#define XS_F (4*KCH*PX)     // 2048 floats per stage ([cq][c][px])
#define MS_F (4*KCH*SPM)    // 4096 floats per stage ([cq][c][slot])
#define PSTR 57
#define ATTN_SMEM ((2*XS_F + 2*MS_F + 2*PX*PSTR + KK2*SS2) * 4)

__global__ void __launch_bounds__(AT) attn_kernel(const float* __restrict__ x,
                                                  const float* __restrict__ Wwd) {
    extern __shared__ __align__(16) float sh[];
    float* xs   = sh;                   // 2*XS_F
    float* ms   = sh + 2*XS_F;          // 2*MS_F
    float* part = ms + 2*MS_F;          // 2*PX*PSTR
    float* wwd  = part + 2*PX*PSTR;     // KK2*SS2

    int t = threadIdx.x;
    int pxp = t & 15;
    int sg  = (t >> 4) & 3;
    int cq  = t >> 6;
    int b = blockIdx.y;
    int n0 = blockIdx.x * PX;

    for (int i = t; i < KK2*SS2; i += AT) wwd[i] = Wwd[i];

    const float* xb = x + (size_t)b*CC*HW + n0;
    const float4* mb4 = (const float4*)(g_M + (size_t)b*CC*SPM);

    int xcq0 = t >> 7,      xr = t & 127;
    int xc = xr >> 3, xq = xr & 7;
    int mc = (t >> 4) & 15, mq = t & 15;

    float4 pf0, pf1, pm0, pm1, pm2, pm3;
    pf0 = *(const float4*)(xb + (size_t)(xcq0*CQG + xc)*HW + xq*4);
    pf1 = *(const float4*)(xb + (size_t)((xcq0+2)*CQG + xc)*HW + xq*4);
    pm0 = mb4[(0*CQG + mc)*16 + mq];
    pm1 = mb4[(1*CQG + mc)*16 + mq];
    pm2 = mb4[(2*CQG + mc)*16 + mq];
    pm3 = mb4[(3*CQG + mc)*16 + mq];
    {
        float4* xs4 = (float4*)xs;
        float4* ms4 = (float4*)ms;
        xs4[t] = pf0; xs4[t+256] = pf1;
        ms4[t] = pm0; ms4[t+256] = pm1; ms4[t+512] = pm2; ms4[t+768] = pm3;
    }

    ull acc0[7], acc1[7];
    #pragma unroll
    for (int j = 0; j < 7; j++) { acc0[j] = 0ULL; acc1[j] = 0ULL; }

    uint32_t xs_sa = (uint32_t)__cvta_generic_to_shared(xs) + (cq*(KCH*PX) + pxp*2)*4;
    uint32_t ms_sa = (uint32_t)__cvta_generic_to_shared(ms) + (cq*(KCH*SPM) + sg*16)*4;

    int p = 0;
    for (int ch = 0; ch < NCH; ch++) {
        __syncthreads();
        if (ch + 1 < NCH) {
            int cb = (ch+1)*KCH;
            pf0 = *(const float4*)(xb + (size_t)(xcq0*CQG + cb + xc)*HW + xq*4);
            pf1 = *(const float4*)(xb + (size_t)((xcq0+2)*CQG + cb + xc)*HW + xq*4);
            pm0 = mb4[(0*CQG + cb + mc)*16 + mq];
            pm1 = mb4[(1*CQG + cb + mc)*16 + mq];
            pm2 = mb4[(2*CQG + cb + mc)*16 + mq];
            pm3 = mb4[(3*CQG + cb + mc)*16 + mq];
        }
        uint32_t xsa = xs_sa + p*(XS_F*4);
        uint32_t msa = ms_sa + p*(MS_F*4);
        #pragma unroll
        for (int c = 0; c < KCH; c++) {
            float xv0, xv1;
            asm("ld.shared.v2.f32 {%0, %1}, [%2];"
                : "=f"(xv0), "=f"(xv1) : "r"(xsa + c*(PX*4)));
            ull ax0 = packf2(xv0, xv0);
            ull ax1 = packf2(xv1, xv1);
            ull m0,m1,m2,m3,m4,m5,m6;
            uint32_t ma = msa + c*(SPM*4);
            asm("ld.shared.v2.u64 {%0, %1}, [%2];" : "=l"(m0), "=l"(m1) : "r"(ma));
            asm("ld.shared.v2.u64 {%0, %1}, [%2];" : "=l"(m2), "=l"(m3) : "r"(ma+16));
            asm("ld.shared.v2.u64 {%0, %1}, [%2];" : "=l"(m4), "=l"(m5) : "r"(ma+32));
            asm("ld.shared.u64 %0, [%1];"          : "=l"(m6)           : "r"(ma+48));
            FMA2(acc0[0], ax0, m0);  FMA2(acc1[0], ax1, m0);
            FMA2(acc0[1], ax0, m1);  FMA2(acc1[1], ax1, m1);
            FMA2(acc0[2], ax0, m2);  FMA2(acc1[2], ax1, m2);
            FMA2(acc0[3], ax0, m3);  FMA2(acc1[3], ax1, m3);
            FMA2(acc0[4], ax0, m4);  FMA2(acc1[4], ax1, m4);
            FMA2(acc0[5], ax0, m5);  FMA2(acc1[5], ax1, m5);
            FMA2(acc0[6], ax0, m6);  FMA2(acc1[6], ax1, m6);
        }
        if (ch + 1 < NCH) {
            float4* xs4 = (float4*)(xs + (1-p)*XS_F);
            float4* ms4 = (float4*)(ms + (1-p)*MS_F);
            xs4[t] = pf0; xs4[t+256] = pf1;
            ms4[t] = pm0; ms4[t+256] = pm1; ms4[t+512] = pm2; ms4[t+768] = pm3;
        }
        p ^= 1;
    }

    // combine quarters: q0,q1 write regions 0,1; q2,q3 add into regions 0,1
    {
        float* pr0 = part + (cq & 1)*(PX*PSTR) + (2*pxp)*PSTR + sg*SEG;
        float* pr1 = pr0 + PSTR;
        if (cq < 2) {
            #pragma unroll
            for (int j = 0; j < 7; j++) {
                float2 v0 = unpackf2(acc0[j]);
                float2 v1 = unpackf2(acc1[j]);
                pr0[2*j] = v0.x; pr0[2*j+1] = v0.y;
                pr1[2*j] = v1.x; pr1[2*j+1] = v1.y;
            }
        }
        __syncthreads();
        if (cq >= 2) {
            #pragma unroll
            for (int j = 0; j < 7; j++) {
                float2 v0 = unpackf2(acc0[j]);
                float2 v1 = unpackf2(acc1[j]);
                pr0[2*j] += v0.x; pr0[2*j+1] += v0.y;
                pr1[2*j] += v1.x; pr1[2*j+1] += v1.y;
            }
        }
    }
    __syncthreads();

    // parallel softmax: 8 threads per pixel (px = t>>3, k = t&7), shfl reduce
    {
        int px = t >> 3, k = t & 7;
        float* row0 = part + px*PSTR;
        const float* row1 = row0 + PX*PSTR;
        float v[7];
        int cnt = (k == 0) ? 7 : 6;     // s = k + 8m < 49
        #pragma unroll
        for (int m = 0; m < 7; m++) {
            int s = k + 8*m;
            v[m] = (s < SS2) ? (row0[s] + row1[s]) : -1e30f;
        }
        float mx = v[0];
        #pragma unroll
        for (int m = 1; m < 7; m++) mx = fmaxf(mx, v[m]);
        mx = fmaxf(mx, __shfl_xor_sync(0xFFFFFFFFu, mx, 1));
        mx = fmaxf(mx, __shfl_xor_sync(0xFFFFFFFFu, mx, 2));
        mx = fmaxf(mx, __shfl_xor_sync(0xFFFFFFFFu, mx, 4));
        float sum = 0.f;
        #pragma unroll
        for (int m = 0; m < 7; m++) {
            if (m < cnt) { v[m] = __expf(v[m] - mx); sum += v[m]; }
        }
        sum += __shfl_xor_sync(0xFFFFFFFFu, sum, 1);
        sum += __shfl_xor_sync(0xFFFFFFFFu, sum, 2);
        sum += __shfl_xor_sync(0xFFFFFFFFu, sum, 4);
        #pragma unroll
        for (int m = 0; m < 7; m++) {
            int s = k + 8*m;
            if (s < SS2) row0[s] = v[m];
        }
        if (k == 0) row0[56] = 1.f / sum;
    }
    __syncthreads();

    // dyn projection (800 outputs over 256 threads)
    for (int idx = t; idx < KK2*PX; idx += AT) {
        int px = idx & 31;
        int j  = idx >> 5;
        const float* ww  = wwd + j*SS2;
        const float* row = part + px*PSTR;
        float d = 0.f;
        #pragma unroll
        for (int s = 0; s < SS2; s++) d += ww[s] * row[s];
        g_dyn[((size_t)b*KK2 + j)*HW + n0 + px] = d * row[56];
    }
}

// ---------------------------------------------------------------------------
// K5 v3 (measured-best, unchanged): f32x2 taps, double-buffered stages.
// ---------------------------------------------------------------------------
#define TT 196
#define TCG 24          // channels per block
#define TST 6           // stages of 4 channels
#define STG_F2 1320     // float2 per stage buffer: 4*11*30

__global__ void __launch_bounds__(TT, 3) taps_kernel(const float* __restrict__ x,
                                                     float* __restrict__ out) {
    __shared__ float2 xs2[2*STG_F2];
    int t = threadIdx.x;
    int rp = t / 28;
    int wp = t % 28;
    int w0 = wp*2;
    int b  = blockIdx.z;
    int h0 = blockIdx.y * 7;
    int c0 = blockIdx.x * TCG;
    int h  = h0 + rp;

    ull dd[KK2];
    #pragma unroll
    for (int j = 0; j < KK2; j++)
        dd[j] = *(const ull*)(g_dyn + ((size_t)b*KK2 + j)*HW + h*WW + w0);

    int sidx[7]; int goff[7]; bool gval[7];
    #pragma unroll
    for (int k = 0; k < 7; k++) {
        int idx = t + TT*k;
        sidx[k] = idx;
        int ci  = idx / 330;
        int rem = idx - ci*330;
        int rr  = rem / 30;
        int q   = rem - rr*30;
        int gr  = h0 + rr - 2;
        int gc  = 2*q - 2;
        gval[k] = (idx < STG_F2) && (gr >= 0) && (gr < HH) && (q >= 1) && (q <= 28);
        goff[k] = ci*HW + gr*WW + gc;
    }

    const float* xb0 = x + (size_t)b*CC*HW + (size_t)c0*HW;
    float* ob = out + (size_t)b*CC*HW;

    float2 pre[7];
    #pragma unroll
    for (int k = 0; k < 7; k++)
        pre[k] = gval[k] ? *(const float2*)(xb0 + goff[k]) : make_float2(0.f, 0.f);
    #pragma unroll
    for (int k = 0; k < 7; k++)
        if (sidx[k] < STG_F2) xs2[sidx[k]] = pre[k];

    int p = 0;
    for (int st = 0; st < TST; st++) {
        __syncthreads();
        if (st + 1 < TST) {
            const float* xsrc = xb0 + (size_t)(st+1)*4*HW;
            #pragma unroll
            for (int k = 0; k < 7; k++)
                pre[k] = gval[k] ? *(const float2*)(xsrc + goff[k]) : make_float2(0.f, 0.f);
        }
        const float* buf = (const float*)(xs2 + p*STG_F2);
        #pragma unroll
        for (int ci = 0; ci < 4; ci++) {
            ull acc = 0ULL;
            #pragma unroll
            for (int i = 0; i < KK; i++) {
                const float* rw = buf + ((ci*11 + rp + i)*60 + w0);
                float2 A  = *(const float2*)rw;
                float2 Bv = *(const float2*)(rw + 2);
                float2 Cv = *(const float2*)(rw + 4);
                ull u0 = packf2(A.x,  A.y);
                ull u1 = packf2(A.y,  Bv.x);
                ull u2 = packf2(Bv.x, Bv.y);
                ull u3 = packf2(Bv.y, Cv.x);
                ull u4 = packf2(Cv.x, Cv.y);
                FMA2(acc, u0, dd[i*5+0]);
                FMA2(acc, u1, dd[i*5+1]);
                FMA2(acc, u2, dd[i*5+2]);
                FMA2(acc, u3, dd[i*5+3]);
                FMA2(acc, u4, dd[i*5+4]);
            }
            float2 o = unpackf2(acc);
            *(float2*)(ob + (size_t)(c0 + st*4 + ci)*HW + h*WW + w0) = o;
        }
        if (st + 1 < TST) {
            float2* dst = xs2 + (1-p)*STG_F2;
            #pragma unroll
            for (int k = 0; k < 7; k++)
                if (sidx[k] < STG_F2) dst[sidx[k]] = pre[k];
        }
        p ^= 1;
    }
}

// ---------------------------------------------------------------------------
extern "C" void kernel_launch(void* const* d_in, const int* in_sizes, int n_in,
                              void* d_out, int out_size) {
    const float* x   = (const float*)d_in[0];
    const float* ctx = (const float*)d_in[1];
    const float* Wq  = (const float*)d_in[2];
    const float* Wk  = (const float*)d_in[3];
    const float* Wwd = (const float*)d_in[4];
    float* out = (float*)d_out;

    static bool attr_set = false;
    if (!attr_set) {
        cudaFuncSetAttribute(attn_kernel,
                             cudaFuncAttributeMaxDynamicSharedMemorySize,
                             ATTN_SMEM);
        attr_set = true;
    }

    pool_kernel<<<BB*CC, 256>>>(ctx);
    kf_kernel<<<(BB*D2*25 + 255)/256, 256>>>(Wk);
    m_kernel<<<(BB*CC*16 + 255)/256, 256>>>(Wq);
    attn_kernel<<<dim3(HW/PX, BB), AT, ATTN_SMEM>>>(x, Wwd);
    taps_kernel<<<dim3(CC/TCG, HH/7, BB), TT>>>(x, out);
}

// round 13
// speedup vs baseline: 1.3337x; 1.3337x over previous
#include <cuda_runtime.h>
#include <cstdint>

typedef unsigned long long ull;

#define BB 4
#define CC 384
#define HH 56
#define WW 56
#define HW (HH*WW)   // 3136
#define KK 5
#define KK2 25
#define SS 7
#define SS2 49
#define D2 192
#define SPM 64       // padded M row: 4 segments x 16 slots (14 real + 2 pad)
#define SEG 14

__device__ __align__(16) float g_ctx_p[BB*CC*SS2];
__device__ __align__(16) float g_kf[BB*D2*SS2];
__device__ __align__(16) float g_M[BB*CC*SPM];
__device__ __align__(16) float g_dyn[BB*KK2*HW];

#define FMA2(acc, a, b) asm("fma.rn.f32x2 %0, %1, %2, %0;" : "+l"(acc) : "l"(a), "l"(b))

__device__ __forceinline__ ull packf2(float lo, float hi) {
    ull r;
    asm("mov.b64 %0, {%1, %2};" : "=l"(r) : "r"(__float_as_uint(lo)), "r"(__float_as_uint(hi)));
    return r;
}
__device__ __forceinline__ float2 unpackf2(ull v) {
    uint32_t l, h;
    asm("mov.b64 {%0, %1}, %2;" : "=r"(l), "=r"(h) : "l"(v));
    float2 r; r.x = __uint_as_float(l); r.y = __uint_as_float(h);
    return r;
}

// ---------------------------------------------------------------------------
// K1 v2 (R10): adaptive avg pool, atomic-free (shfl reduce).
// ---------------------------------------------------------------------------
__global__ void __launch_bounds__(256) pool_kernel(const float* __restrict__ ctx) {
    __shared__ float part[HH][SS];
    int t = threadIdx.x;
    int w = t >> 5;
    int l = t & 31;
    int bc = blockIdx.x;
    const float* p = ctx + (size_t)bc * HW;

    #pragma unroll
    for (int it = 0; it < 7; it++) {
        int h = w + it*8;
        float v = 0.f;
        if (l < 28) {
            float2 d2 = *(const float2*)(p + h*WW + 2*l);
            v = d2.x + d2.y;
        }
        v += __shfl_xor_sync(0xFFFFFFFFu, v, 1);
        v += __shfl_xor_sync(0xFFFFFFFFu, v, 2);
        if (l < 28 && (l & 3) == 0)
            part[h][l >> 2] = v;
    }
    __syncthreads();
    if (t < SS2) {
        int s1 = t / SS, s2 = t - s1*SS;
        float s = 0.f;
        #pragma unroll
        for (int i = 0; i < 8; i++) s += part[s1*8 + i][s2];
        g_ctx_p[(size_t)bc * SS2 + t] = s * (1.f/64.f);
    }
}

// ---------------------------------------------------------------------------
// K2 v1 (R10): kf[b,d,s] = sum_c Wk[d,c] * ctx_p[b,c,s]
// ---------------------------------------------------------------------------
__global__ void kf_kernel(const float* __restrict__ Wk) {
    int id = blockIdx.x * blockDim.x + threadIdx.x;
    if (id >= BB*D2*SS2) return;
    int s = id % SS2;
    int d = (id / SS2) % D2;
    int b = id / (SS2*D2);
    const float* wk = Wk + (size_t)d * CC;
    const float* cp = g_ctx_p + (size_t)b * CC * SS2 + s;
    float acc = 0.f;
    #pragma unroll 8
    for (int c = 0; c < CC; c++) acc += wk[c] * cp[(size_t)c * SS2];
    g_kf[id] = acc;
}

// ---------------------------------------------------------------------------
// K3 v1 (R10): M[b,c,slot], slot = sg*16+k -> s = sg*14+k (k<14, s<49)
// ---------------------------------------------------------------------------
__global__ void m_kernel(const float* __restrict__ Wq) {
    int id = blockIdx.x * blockDim.x + threadIdx.x;
    if (id >= BB*CC*SPM) return;
    int slot = id % SPM;
    int c = (id / SPM) % CC;
    int b = id / (SPM*CC);
    int sg = slot >> 4, k = slot & 15;
    int s = sg*SEG + k;
    float acc = 0.f;
    if (k < SEG && s < SS2) {
        const float* kf = g_kf + (size_t)b * D2 * SS2 + s;
        #pragma unroll 8
        for (int d = 0; d < D2; d++) acc += Wq[(size_t)d * CC + c] * kf[(size_t)d * SS2];
    }
    g_M[id] = acc;
}

// ---------------------------------------------------------------------------
// K4 v7 (R11, measured 25.2us): PX=32, 256 threads, parallel softmax.
// ---------------------------------------------------------------------------
#define PX 32
#define AT 256
#define KCH 16
#define NCH 6
#define CQG 96
#define XS_F (4*KCH*PX)
#define MS_F (4*KCH*SPM)
#define PSTR 57
#define ATTN_SMEM ((2*XS_F + 2*MS_F + 2*PX*PSTR + KK2*SS2) * 4)

__global__ void __launch_bounds__(AT) attn_kernel(const float* __restrict__ x,
                                                  const float* __restrict__ Wwd) {
    extern __shared__ __align__(16) float sh[];
    float* xs   = sh;
    float* ms   = sh + 2*XS_F;
    float* part = ms + 2*MS_F;
    float* wwd  = part + 2*PX*PSTR;

    int t = threadIdx.x;
    int pxp = t & 15;
    int sg  = (t >> 4) & 3;
    int cq  = t >> 6;
    int b = blockIdx.y;
    int n0 = blockIdx.x * PX;

    for (int i = t; i < KK2*SS2; i += AT) wwd[i] = Wwd[i];

    const float* xb = x + (size_t)b*CC*HW + n0;
    const float4* mb4 = (const float4*)(g_M + (size_t)b*CC*SPM);

    int xcq0 = t >> 7,      xr = t & 127;
    int xc = xr >> 3, xq = xr & 7;
    int mc = (t >> 4) & 15, mq = t & 15;

    float4 pf0, pf1, pm0, pm1, pm2, pm3;
    pf0 = *(const float4*)(xb + (size_t)(xcq0*CQG + xc)*HW + xq*4);
    pf1 = *(const float4*)(xb + (size_t)((xcq0+2)*CQG + xc)*HW + xq*4);
    pm0 = mb4[(0*CQG + mc)*16 + mq];
    pm1 = mb4[(1*CQG + mc)*16 + mq];
    pm2 = mb4[(2*CQG + mc)*16 + mq];
    pm3 = mb4[(3*CQG + mc)*16 + mq];
    {
        float4* xs4 = (float4*)xs;
        float4* ms4 = (float4*)ms;
        xs4[t] = pf0; xs4[t+256] = pf1;
        ms4[t] = pm0; ms4[t+256] = pm1; ms4[t+512] = pm2; ms4[t+768] = pm3;
    }

    ull acc0[7], acc1[7];
    #pragma unroll
    for (int j = 0; j < 7; j++) { acc0[j] = 0ULL; acc1[j] = 0ULL; }

    uint32_t xs_sa = (uint32_t)__cvta_generic_to_shared(xs) + (cq*(KCH*PX) + pxp*2)*4;
    uint32_t ms_sa = (uint32_t)__cvta_generic_to_shared(ms) + (cq*(KCH*SPM) + sg*16)*4;

    int p = 0;
    for (int ch = 0; ch < NCH; ch++) {
        __syncthreads();
        if (ch + 1 < NCH) {
            int cb = (ch+1)*KCH;
            pf0 = *(const float4*)(xb + (size_t)(xcq0*CQG + cb + xc)*HW + xq*4);
            pf1 = *(const float4*)(xb + (size_t)((xcq0+2)*CQG + cb + xc)*HW + xq*4);
            pm0 = mb4[(0*CQG + cb + mc)*16 + mq];
            pm1 = mb4[(1*CQG + cb + mc)*16 + mq];
            pm2 = mb4[(2*CQG + cb + mc)*16 + mq];
            pm3 = mb4[(3*CQG + cb + mc)*16 + mq];
        }
        uint32_t xsa = xs_sa + p*(XS_F*4);
        uint32_t msa = ms_sa + p*(MS_F*4);
        #pragma unroll
        for (int c = 0; c < KCH; c++) {
            float xv0, xv1;
            asm("ld.shared.v2.f32 {%0, %1}, [%2];"
                : "=f"(xv0), "=f"(xv1) : "r"(xsa + c*(PX*4)));
            ull ax0 = packf2(xv0, xv0);
            ull ax1 = packf2(xv1, xv1);
            ull m0,m1,m2,m3,m4,m5,m6;
            uint32_t ma = msa + c*(SPM*4);
            asm("ld.shared.v2.u64 {%0, %1}, [%2];" : "=l"(m0), "=l"(m1) : "r"(ma));
            asm("ld.shared.v2.u64 {%0, %1}, [%2];" : "=l"(m2), "=l"(m3) : "r"(ma+16));
            asm("ld.shared.v2.u64 {%0, %1}, [%2];" : "=l"(m4), "=l"(m5) : "r"(ma+32));
            asm("ld.shared.u64 %0, [%1];"          : "=l"(m6)           : "r"(ma+48));
            FMA2(acc0[0], ax0, m0);  FMA2(acc1[0], ax1, m0);
            FMA2(acc0[1], ax0, m1);  FMA2(acc1[1], ax1, m1);
            FMA2(acc0[2], ax0, m2);  FMA2(acc1[2], ax1, m2);
            FMA2(acc0[3], ax0, m3);  FMA2(acc1[3], ax1, m3);
            FMA2(acc0[4], ax0, m4);  FMA2(acc1[4], ax1, m4);
            FMA2(acc0[5], ax0, m5);  FMA2(acc1[5], ax1, m5);
            FMA2(acc0[6], ax0, m6);  FMA2(acc1[6], ax1, m6);
        }
        if (ch + 1 < NCH) {
            float4* xs4 = (float4*)(xs + (1-p)*XS_F);
            float4* ms4 = (float4*)(ms + (1-p)*MS_F);
            xs4[t] = pf0; xs4[t+256] = pf1;
            ms4[t] = pm0; ms4[t+256] = pm1; ms4[t+512] = pm2; ms4[t+768] = pm3;
        }
        p ^= 1;
    }

    {
        float* pr0 = part + (cq & 1)*(PX*PSTR) + (2*pxp)*PSTR + sg*SEG;
        float* pr1 = pr0 + PSTR;
        if (cq < 2) {
            #pragma unroll
            for (int j = 0; j < 7; j++) {
                float2 v0 = unpackf2(acc0[j]);
                float2 v1 = unpackf2(acc1[j]);
                pr0[2*j] = v0.x; pr0[2*j+1] = v0.y;
                pr1[2*j] = v1.x; pr1[2*j+1] = v1.y;
            }
        }
        __syncthreads();
        if (cq >= 2) {
            #pragma unroll
            for (int j = 0; j < 7; j++) {
                float2 v0 = unpackf2(acc0[j]);
                float2 v1 = unpackf2(acc1[j]);
                pr0[2*j] += v0.x; pr0[2*j+1] += v0.y;
                pr1[2*j] += v1.x; pr1[2*j+1] += v1.y;
            }
        }
    }
    __syncthreads();

    // parallel softmax: 8 threads per pixel
    {
        int px = t >> 3, k = t & 7;
        float* row0 = part + px*PSTR;
        const float* row1 = row0 + PX*PSTR;
        float v[7];
        int cnt = (k == 0) ? 7 : 6;
        #pragma unroll
        for (int m = 0; m < 7; m++) {
            int s = k + 8*m;
            v[m] = (s < SS2) ? (row0[s] + row1[s]) : -1e30f;
        }
        float mx = v[0];
        #pragma unroll
        for (int m = 1; m < 7; m++) mx = fmaxf(mx, v[m]);
        mx = fmaxf(mx, __shfl_xor_sync(0xFFFFFFFFu, mx, 1));
        mx = fmaxf(mx, __shfl_xor_sync(0xFFFFFFFFu, mx, 2));
        mx = fmaxf(mx, __shfl_xor_sync(0xFFFFFFFFu, mx, 4));
        float sum = 0.f;
        #pragma unroll
        for (int m = 0; m < 7; m++) {
            if (m < cnt) { v[m] = __expf(v[m] - mx); sum += v[m]; }
        }
        sum += __shfl_xor_sync(0xFFFFFFFFu, sum, 1);
        sum += __shfl_xor_sync(0xFFFFFFFFu, sum, 2);
        sum += __shfl_xor_sync(0xFFFFFFFFu, sum, 4);
        #pragma unroll
        for (int m = 0; m < 7; m++) {
            int s = k + 8*m;
            if (s < SS2) row0[s] = v[m];
        }
        if (k == 0) row0[56] = 1.f / sum;
    }
    __syncthreads();

    for (int idx = t; idx < KK2*PX; idx += AT) {
        int px = idx & 31;
        int j  = idx >> 5;
        const float* ww  = wwd + j*SS2;
        const float* row = part + px*PSTR;
        float d = 0.f;
        #pragma unroll
        for (int s = 0; s < SS2; s++) d += ww[s] * row[s];
        g_dyn[((size_t)b*KK2 + j)*HW + n0 + px] = d * row[56];
    }
}

// ---------------------------------------------------------------------------
// K5 v6: f32x2 taps with parity pack-elimination.
// Taps j=0,2,4 use aligned float2 directly (L0,L1,L2); only j=1,3 pack.
// Otherwise identical to R10's measured-best v3 (double-buffered stages).
// ---------------------------------------------------------------------------
#define TT 196
#define TCG 24          // channels per block
#define TST 6           // stages of 4 channels
#define STG_F2 1320     // float2 per stage buffer: 4*11*30

__global__ void __launch_bounds__(TT, 3) taps_kernel(const float* __restrict__ x,
                                                     float* __restrict__ out) {
    __shared__ float2 xs2[2*STG_F2];
    int t = threadIdx.x;
    int rp = t / 28;
    int wp = t % 28;
    int w0 = wp*2;
    int b  = blockIdx.z;
    int h0 = blockIdx.y * 7;
    int c0 = blockIdx.x * TCG;
    int h  = h0 + rp;

    ull dd[KK2];
    #pragma unroll
    for (int j = 0; j < KK2; j++)
        dd[j] = *(const ull*)(g_dyn + ((size_t)b*KK2 + j)*HW + h*WW + w0);

    int sidx[7]; int goff[7]; bool gval[7];
    #pragma unroll
    for (int k = 0; k < 7; k++) {
        int idx = t + TT*k;
        sidx[k] = idx;
        int ci  = idx / 330;
        int rem = idx - ci*330;
        int rr  = rem / 30;
        int q   = rem - rr*30;
        int gr  = h0 + rr - 2;
        int gc  = 2*q - 2;
        gval[k] = (idx < STG_F2) && (gr >= 0) && (gr < HH) && (q >= 1) && (q <= 28);
        goff[k] = ci*HW + gr*WW + gc;
    }

    const float* xb0 = x + (size_t)b*CC*HW + (size_t)c0*HW;
    float* ob = out + (size_t)b*CC*HW;

    float2 pre[7];
    #pragma unroll
    for (int k = 0; k < 7; k++)
        pre[k] = gval[k] ? *(const float2*)(xb0 + goff[k]) : make_float2(0.f, 0.f);
    #pragma unroll
    for (int k = 0; k < 7; k++)
        if (sidx[k] < STG_F2) xs2[sidx[k]] = pre[k];

    int p = 0;
    for (int st = 0; st < TST; st++) {
        __syncthreads();
        if (st + 1 < TST) {
            const float* xsrc = xb0 + (size_t)(st+1)*4*HW;
            #pragma unroll
            for (int k = 0; k < 7; k++)
                pre[k] = gval[k] ? *(const float2*)(xsrc + goff[k]) : make_float2(0.f, 0.f);
        }
        const float* buf = (const float*)(xs2 + p*STG_F2);
        #pragma unroll
        for (int ci = 0; ci < 4; ci++) {
            ull acc = 0ULL;
            #pragma unroll
            for (int i = 0; i < KK; i++) {
                // buf float-index f corresponds to gc = f-2; w0 even so all
                // three 8B loads are aligned float2 (ull) reads.
                const ull* rw2 = (const ull*)(buf + ((ci*11 + rp + i)*60 + w0));
                ull L0 = rw2[0];     // taps j=0: (w0-2, w0-1)
                ull L1 = rw2[1];     // taps j=2: (w0,   w0+1)
                ull L2 = rw2[2];     // taps j=4: (w0+2, w0+3)
                float2 a = unpackf2(L0);
                float2 bv = unpackf2(L1);
                float2 cv = unpackf2(L2);
                ull u1 = packf2(a.y,  bv.x);   // j=1: (w0-1, w0)
                ull u3 = packf2(bv.y, cv.x);   // j=3: (w0+1, w0+2)
                FMA2(acc, L0, dd[i*5+0]);
                FMA2(acc, u1, dd[i*5+1]);
                FMA2(acc, L1, dd[i*5+2]);
                FMA2(acc, u3, dd[i*5+3]);
                FMA2(acc, L2, dd[i*5+4]);
            }
            float2 o = unpackf2(acc);
            *(float2*)(ob + (size_t)(c0 + st*4 + ci)*HW + h*WW + w0) = o;
        }
        if (st + 1 < TST) {
            float2* dst = xs2 + (1-p)*STG_F2;
            #pragma unroll
            for (int k = 0; k < 7; k++)
                if (sidx[k] < STG_F2) dst[sidx[k]] = pre[k];
        }
        p ^= 1;
    }
}

// ---------------------------------------------------------------------------
extern "C" void kernel_launch(void* const* d_in, const int* in_sizes, int n_in,
                              void* d_out, int out_size) {
    const float* x   = (const float*)d_in[0];
    const float* ctx = (const float*)d_in[1];
    const float* Wq  = (const float*)d_in[2];
    const float* Wk  = (const float*)d_in[3];
    const float* Wwd = (const float*)d_in[4];
    float* out = (float*)d_out;

    static bool attr_set = false;
    if (!attr_set) {
        cudaFuncSetAttribute(attn_kernel,
                             cudaFuncAttributeMaxDynamicSharedMemorySize,
                             ATTN_SMEM);
        attr_set = true;
    }

    pool_kernel<<<BB*CC, 256>>>(ctx);
    kf_kernel<<<(BB*D2*SS2 + 255)/256, 256>>>(Wk);
    m_kernel<<<(BB*CC*SPM + 255)/256, 256>>>(Wq);
    attn_kernel<<<dim3(HW/PX, BB), AT, ATTN_SMEM>>>(x, Wwd);
    taps_kernel<<<dim3(CC/TCG, HH/7, BB), TT>>>(x, out);
}